// round 8
// baseline (speedup 1.0000x reference)
#include <cuda_runtime.h>
#include <stdint.h>

#define ATT     1024
#define GM1     14          // groups actually written (G-1)
#define LP1     16          // rows per class
#define GSIZE   64
#define NCLASS  6000
#define NUNSEEN 1200
#define NSEEN   4800
#define CPB     4           // classes per tile (full attr row per tile)

#define TIL_GZSL (NCLASS  / CPB)   // 1500
#define TIL_SEEN (NSEEN   / CPB)   // 1200
#define TIL_ZSL  (NUNSEEN / CPB)   // 300
#define TIL_TOTAL (TIL_GZSL + TIL_SEEN + TIL_ZSL)  // 3000

#define GRID_BLOCKS (148 * 8)      // persistent: fills 8 blocks/SM

// ---------------------------------------------------------------------------
// Persistent fused kernel. Each block: one-time mask/ballot setup, then loops
// over tiles (4 classes x 1024 attrs each):
//   load 4 attr rows -> 8-warp norm computation -> 256 KB streaming stores.
// ---------------------------------------------------------------------------
__global__ void __launch_bounds__(256, 8) k_all(
    const float* __restrict__ attr,
    const float* __restrict__ betas,
    const int*   __restrict__ group_cols,
    const int*   __restrict__ unseen,
    const int*   __restrict__ seen,
    float* __restrict__ out)
{
    __shared__ float    s_attr[CPB][ATT];       // 16 KB
    __shared__ uint32_t s_mask[ATT];            // 4 KB
    __shared__ float    s_red [8][15];
    __shared__ float    s_inv [CPB][LP1];
    __shared__ float    s_beta[LP1];
    __shared__ float    s_cb2 [GM1];
    __shared__ int      s_cnt [GM1];
    __shared__ int      s_cls [CPB];

    const int t    = threadIdx.x;
    const int w    = t >> 5;
    const int lane = t & 31;

    // ================= one-time setup =================
#pragma unroll
    for (int i = 0; i < 4; ++i) s_mask[i * 256 + t] = 0u;
    if (t < GM1)           s_cnt[t] = 0;
    if (t >= 16 && t < 32) s_beta[t - 16] = (t < 18) ? 0.f : __ldg(betas + t - 18);
    __syncthreads();

    for (int i = t; i < GM1 * GSIZE; i += 256) {
        int col = __ldg(group_cols + i);
        atomicOr(&s_mask[col], 1u << ((i >> 6) + 2));
    }
    __syncthreads();

#pragma unroll
    for (int i = 0; i < 4; ++i) {
        uint32_t m = s_mask[i * 256 + t];
#pragma unroll
        for (int g = 0; g < GM1; ++g) {
            uint32_t bal = __ballot_sync(0xffffffffu, m & (1u << (g + 2)));
            if (lane == 0 && bal) atomicAdd(&s_cnt[g], __popc(bal));
        }
    }
    __syncthreads();
    if (t < GM1) s_cb2[t] = (float)s_cnt[t] * s_beta[t + 2] * s_beta[t + 2];

    // per-thread store-phase constants (tile-invariant)
    const int half = lane >> 4;          // attr row parity within warp
    const int ci   = (lane >> 2) & 3;    // class within tile
    const int q    = lane & 3;           // layer quad
    const int abase = (w << 1) + half;   // 0..15
    const float b0 = (4 * q + 0 < 2) ? 0.f : __ldg(betas + 4 * q + 0 - 2);
    const float b1 = __ldg(betas + 4 * q + 1 - 2);
    const float b2 = __ldg(betas + 4 * q + 2 - 2);
    const float b3 = __ldg(betas + 4 * q + 3 - 2);
    // (q==0 -> layers 0..3: layers 0,1 have beta 0; handled: b0 above, b1 below)
    const float b1f = (4 * q + 1 < 2) ? 0.f : b1;

    // ================= tile loop =================
    for (int tile = blockIdx.x; tile < TIL_TOTAL; tile += GRID_BLOCKS) {
        // segment decode (largest first)
        int b = tile;
        const int* map;
        int nclass;
        float* obaseseg;
        if (b < TIL_GZSL) {
            map = nullptr; nclass = NCLASS;
            obaseseg = out + (size_t)ATT * (NUNSEEN + NSEEN) * LP1;
        } else if (b < TIL_GZSL + TIL_SEEN) {
            b -= TIL_GZSL;
            map = seen; nclass = NSEEN;
            obaseseg = out + (size_t)ATT * NUNSEEN * LP1;
        } else {
            b -= TIL_GZSL + TIL_SEEN;
            map = unseen; nclass = NUNSEEN;
            obaseseg = out;
        }
        const int c0 = b * CPB;
        const int stride = nclass * LP1;

        if (t < CPB) s_cls[t] = map ? __ldg(map + c0 + t) : (c0 + t);
        __syncthreads();   // s_attr free from prev tile; s_cls visible

        // ---- stage 4 attr rows (1024 float4, 4 per thread) ----
#pragma unroll
        for (int i = 0; i < 4; ++i) {
            int idx = i * 256 + t;
            int cc  = idx >> 8;
            int j   = idx & 255;
            float4 v = __ldg((const float4*)(attr + (size_t)s_cls[cc] * ATT) + j);
            s_attr[cc][j * 4 + 0] = v.x; s_attr[cc][j * 4 + 1] = v.y;
            s_attr[cc][j * 4 + 2] = v.z; s_attr[cc][j * 4 + 3] = v.w;
        }
        __syncthreads();

        // ---- norms: warp w handles class w>>1, half w&1 (512 elems) ----
        {
            const int nc = w >> 1;
            const int hb = (w & 1) * 512;
            float tot = 0.f;
            float gs[GM1];
#pragma unroll
            for (int g = 0; g < GM1; ++g) gs[g] = 0.f;
#pragma unroll
            for (int j = 0; j < 16; ++j) {
                int a = hb + j * 32 + lane;
                float v  = s_attr[nc][a];
                float v2 = v * v;
                tot += v2;
                uint32_t m = s_mask[a];
#pragma unroll
                for (int g = 0; g < GM1; ++g)
                    if (m & (1u << (g + 2))) gs[g] += v2;
            }
#pragma unroll
            for (int o = 16; o; o >>= 1) {
                tot += __shfl_xor_sync(0xffffffffu, tot, o);
#pragma unroll
                for (int g = 0; g < GM1; ++g)
                    gs[g] += __shfl_xor_sync(0xffffffffu, gs[g], o);
            }
            if (lane == 0) {
                s_red[w][0] = tot;
#pragma unroll
                for (int g = 0; g < GM1; ++g) s_red[w][g + 1] = gs[g];
            }
        }
        __syncthreads();
        if (t < CPB * LP1) {
            int nc = t >> 4, l = t & 15;
            float tt = s_red[2 * nc][0] + s_red[2 * nc + 1][0];
            float x  = (l < 2) ? tt
                               : tt - (s_red[2 * nc][l - 1] + s_red[2 * nc + 1][l - 1])
                                    + s_cb2[l - 2];
            s_inv[nc][l] = 1.0f / fmaxf(sqrtf(x), 1e-12f);
        }
        __syncthreads();

        // ---- streaming transposed write (strength-reduced addresses) ----
        const float i0 = s_inv[ci][4 * q + 0], i1 = s_inv[ci][4 * q + 1];
        const float i2 = s_inv[ci][4 * q + 2], i3 = s_inv[ci][4 * q + 3];

        float* p = obaseseg + (size_t)(c0 + ci) * LP1 + 4 * q
                            + (size_t)abase * stride;
        const size_t step = (size_t)stride * 16;
        const float* arow = s_attr[ci];

#pragma unroll 8
        for (int it = 0; it < ATT / 16; ++it) {   // 64 iterations
            int a = it * 16 + abase;
            uint32_t m = s_mask[a] >> (4 * q);
            float av = arow[a];
            float4 v;
            v.x = ((m & 1u) ? b0  : av) * i0;
            v.y = ((m & 2u) ? b1f : av) * i1;
            v.z = ((m & 4u) ? b2  : av) * i2;
            v.w = ((m & 8u) ? b3  : av) * i3;
            __stcs((float4*)p, v);
            p += step;
        }
    }
}

// ---------------------------------------------------------------------------
extern "C" void kernel_launch(void* const* d_in, const int* in_sizes, int n_in,
                              void* d_out, int out_size) {
    const float* attribute  = (const float*)d_in[0];
    const float* betas      = (const float*)d_in[1];
    const int*   group_cols = (const int*)d_in[2];
    const int*   unseen     = (const int*)d_in[3];
    const int*   seen       = (const int*)d_in[4];
    float* out = (float*)d_out;

    k_all<<<GRID_BLOCKS, 256>>>(attribute, betas, group_cols, unseen, seen, out);
}

// round 9
// speedup vs baseline: 1.0998x; 1.0998x over previous
#include <cuda_runtime.h>
#include <stdint.h>

#define ATT     1024
#define GM1     14          // groups actually written (G-1)
#define LP1     16          // rows per class
#define GSIZE   64
#define NCLASS  6000
#define NUNSEEN 1200
#define NSEEN   4800
#define CPB     4           // classes per block (full attr row per block)

#define BLK_GZSL (NCLASS  / CPB)   // 1500
#define BLK_SEEN (NSEEN   / CPB)   // 1200
#define BLK_ZSL  (NUNSEEN / CPB)   // 300
#define BLK_TOTAL (BLK_GZSL + BLK_SEEN + BLK_ZSL)  // 3000

// ---------------------------------------------------------------------------
// Single fused kernel (non-persistent; block churn hides prologues).
// Per block: 4 classes x 1024 attrs.
//   mask rebuild + 4 attr rows staged -> 8-warp norm -> 256 KB streaming
//   stores with strength-reduced addressing.
// ---------------------------------------------------------------------------
__global__ void __launch_bounds__(256, 8) k_all(
    const float* __restrict__ attr,
    const float* __restrict__ betas,
    const int*   __restrict__ group_cols,
    const int*   __restrict__ unseen,
    const int*   __restrict__ seen,
    float* __restrict__ out)
{
    // ---- segment decode (largest first) ----
    int b = blockIdx.x;
    const int* map;
    int nclass;
    float* obaseseg;
    if (b < BLK_GZSL) {
        map = nullptr; nclass = NCLASS;
        obaseseg = out + (size_t)ATT * (NUNSEEN + NSEEN) * LP1;
    } else if (b < BLK_GZSL + BLK_SEEN) {
        b -= BLK_GZSL;
        map = seen; nclass = NSEEN;
        obaseseg = out + (size_t)ATT * NUNSEEN * LP1;
    } else {
        b -= BLK_GZSL + BLK_SEEN;
        map = unseen; nclass = NUNSEEN;
        obaseseg = out;
    }
    const int c0 = b * CPB;
    const int stride = nclass * LP1;

    __shared__ float    s_attr[CPB][ATT];       // 16 KB
    __shared__ uint32_t s_mask[ATT];            // 4 KB
    __shared__ float    s_red [8][15];
    __shared__ float    s_inv [CPB][LP1];
    __shared__ float    s_cb2 [GM1];
    __shared__ float    s_beta[LP1];
    __shared__ int      s_cnt [GM1];
    __shared__ int      s_cls [CPB];

    const int t    = threadIdx.x;
    const int w    = t >> 5;
    const int lane = t & 31;

    // ---- init ----
#pragma unroll
    for (int i = 0; i < 4; ++i) s_mask[i * 256 + t] = 0u;
    if (t < GM1)              s_cnt[t] = 0;
    if (t < CPB)              s_cls[t] = map ? __ldg(map + c0 + t) : (c0 + t);
    if (t >= 16 && t < 32)    s_beta[t - 16] = (t < 18) ? 0.f : __ldg(betas + t - 18);
    __syncthreads();

    // ---- mask rebuild (896 entries) + attr tile (1024 float4) ----
    for (int i = t; i < GM1 * GSIZE; i += 256) {
        int col = __ldg(group_cols + i);
        atomicOr(&s_mask[col], 1u << ((i >> 6) + 2));
    }
#pragma unroll
    for (int i = 0; i < 4; ++i) {
        int idx = i * 256 + t;            // 0..1023 float4 slots
        int cc  = idx >> 8;               // class 0..3
        int j   = idx & 255;              // float4 within row
        float4 v = __ldg((const float4*)(attr + (size_t)s_cls[cc] * ATT) + j);
        s_attr[cc][j * 4 + 0] = v.x; s_attr[cc][j * 4 + 1] = v.y;
        s_attr[cc][j * 4 + 2] = v.z; s_attr[cc][j * 4 + 3] = v.w;
    }
    __syncthreads();

    // ---- distinct counts via ballots ----
#pragma unroll
    for (int i = 0; i < 4; ++i) {
        uint32_t m = s_mask[i * 256 + t];
#pragma unroll
        for (int g = 0; g < GM1; ++g) {
            uint32_t bal = __ballot_sync(0xffffffffu, m & (1u << (g + 2)));
            if (lane == 0 && bal) atomicAdd(&s_cnt[g], __popc(bal));
        }
    }
    __syncthreads();
    if (t < GM1) s_cb2[t] = (float)s_cnt[t] * s_beta[t + 2] * s_beta[t + 2];
    __syncthreads();

    // ---- norms: warp w handles class w>>1, half w&1 (512 elems each) ----
    {
        const int nc = w >> 1;
        const int hb = (w & 1) * 512;
        float tot = 0.f;
        float gs[GM1];
#pragma unroll
        for (int g = 0; g < GM1; ++g) gs[g] = 0.f;
#pragma unroll
        for (int j = 0; j < 16; ++j) {
            int a = hb + j * 32 + lane;
            float v  = s_attr[nc][a];
            float v2 = v * v;
            tot += v2;
            uint32_t m = s_mask[a];
#pragma unroll
            for (int g = 0; g < GM1; ++g)
                if (m & (1u << (g + 2))) gs[g] += v2;
        }
#pragma unroll
        for (int o = 16; o; o >>= 1) {
            tot += __shfl_xor_sync(0xffffffffu, tot, o);
#pragma unroll
            for (int g = 0; g < GM1; ++g)
                gs[g] += __shfl_xor_sync(0xffffffffu, gs[g], o);
        }
        if (lane == 0) {
            s_red[w][0] = tot;
#pragma unroll
            for (int g = 0; g < GM1; ++g) s_red[w][g + 1] = gs[g];
        }
    }
    __syncthreads();
    if (t < CPB * LP1) {
        int nc = t >> 4, l = t & 15;
        float tt = s_red[2 * nc][0] + s_red[2 * nc + 1][0];
        float x  = (l < 2) ? tt
                           : tt - (s_red[2 * nc][l - 1] + s_red[2 * nc + 1][l - 1])
                                + s_cb2[l - 2];
        s_inv[nc][l] = 1.0f / fmaxf(sqrtf(x), 1e-12f);
    }
    __syncthreads();

    // ---- streaming transposed write (strength-reduced addressing) ----
    // lane: half = lane>>4, ci = (lane>>2)&3, q = lane&3.
    const int half = lane >> 4;
    const int ci   = (lane >> 2) & 3;
    const int q    = lane & 3;
    const int abase = (w << 1) + half;    // 0..15

    const float b0 = s_beta[4 * q + 0], b1 = s_beta[4 * q + 1];
    const float b2 = s_beta[4 * q + 2], b3 = s_beta[4 * q + 3];
    const float i0 = s_inv[ci][4 * q + 0], i1 = s_inv[ci][4 * q + 1];
    const float i2 = s_inv[ci][4 * q + 2], i3 = s_inv[ci][4 * q + 3];

    float* p = obaseseg + (size_t)(c0 + ci) * LP1 + 4 * q
                        + (size_t)abase * stride;
    const size_t step = (size_t)stride * 16;
    const float* arow = s_attr[ci];

#pragma unroll 8
    for (int it = 0; it < ATT / 16; ++it) {   // 64 iterations
        int a = it * 16 + abase;
        uint32_t m = s_mask[a] >> (4 * q);
        float av = arow[a];
        float4 v;
        v.x = ((m & 1u) ? b0 : av) * i0;
        v.y = ((m & 2u) ? b1 : av) * i1;
        v.z = ((m & 4u) ? b2 : av) * i2;
        v.w = ((m & 8u) ? b3 : av) * i3;
        __stcs((float4*)p, v);
        p += step;
    }
}

// ---------------------------------------------------------------------------
extern "C" void kernel_launch(void* const* d_in, const int* in_sizes, int n_in,
                              void* d_out, int out_size) {
    const float* attribute  = (const float*)d_in[0];
    const float* betas      = (const float*)d_in[1];
    const int*   group_cols = (const int*)d_in[2];
    const int*   unseen     = (const int*)d_in[3];
    const int*   seen       = (const int*)d_in[4];
    float* out = (float*)d_out;

    k_all<<<BLK_TOTAL, 256>>>(attribute, betas, group_cols, unseen, seen, out);
}